// round 9
// baseline (speedup 1.0000x reference)
#include <cuda_runtime.h>
#include <math.h>

#define N_NODES 100000
#define N_EDGES 800000
#define F 128
#define SCAN_B 1024
#define NB_SCAN ((N_NODES + SCAN_B - 1) / SCAN_B)   // 98

// ---------------- static scratch (allocation-free rule) ----------------
__device__ int   g_deg[N_NODES];
__device__ float g_dinv[N_NODES];
__device__ int   g_off[N_NODES + 1];
__device__ int   g_cursor[N_NODES];
__device__ int   g_src[N_EDGES];
__device__ int   g_bsum[NB_SCAN + 32];
__device__ float g_h1[(size_t)N_NODES * F];

// ---------------- degree count ----------------
__global__ void k_count(const int* __restrict__ ei) {
    int e = blockIdx.x * blockDim.x + threadIdx.x;
    if (e < N_EDGES) {
        int col = ei[N_EDGES + e];
        if ((unsigned)col < (unsigned)N_NODES)
            atomicAdd(&g_deg[col], 1);
    }
}

// ---------------- exclusive scan of g_deg -> g_off ----------------
__global__ void k_scan1() {
    __shared__ int s[SCAN_B];
    int i = blockIdx.x * SCAN_B + threadIdx.x;
    int v = (i < N_NODES) ? g_deg[i] : 0;
    s[threadIdx.x] = v;
    __syncthreads();
    for (int off = 1; off < SCAN_B; off <<= 1) {
        int t = 0;
        if (threadIdx.x >= off) t = s[threadIdx.x - off];
        __syncthreads();
        if (threadIdx.x >= off) s[threadIdx.x] += t;
        __syncthreads();
    }
    if (i < N_NODES) g_off[i] = s[threadIdx.x] - v;  // partial exclusive
    if (threadIdx.x == SCAN_B - 1) g_bsum[blockIdx.x] = s[threadIdx.x];
}

// parallel scan of the 98 block sums (one block, Hillis-Steele)
__global__ void k_scan2() {
    __shared__ int s[128];
    int t = threadIdx.x;
    int v = (t < NB_SCAN) ? g_bsum[t] : 0;
    s[t] = v;
    __syncthreads();
#pragma unroll
    for (int off = 1; off < 128; off <<= 1) {
        int u = 0;
        if (t >= off) u = s[t - off];
        __syncthreads();
        if (t >= off) s[t] += u;
        __syncthreads();
    }
    if (t < NB_SCAN) g_bsum[t] = s[t] - v;  // exclusive
}

__global__ void k_scan3() {
    int i = blockIdx.x * blockDim.x + threadIdx.x;
    if (i < N_NODES) {
        int off = g_off[i] + g_bsum[i / SCAN_B];
        g_off[i] = off;
        g_cursor[i] = off;
        // dinv: degree includes self loop (+1)
        g_dinv[i] = rsqrtf((float)(g_deg[i] + 1));
    }
    if (i == 0) g_off[N_NODES] = N_EDGES;
}

// ---------------- place edges into CSR (by destination) ----------------
__global__ void k_place(const int* __restrict__ ei) {
    int e = blockIdx.x * blockDim.x + threadIdx.x;
    if (e < N_EDGES) {
        int row = ei[e];
        int col = ei[N_EDGES + e];
        if ((unsigned)row < (unsigned)N_NODES && (unsigned)col < (unsigned)N_NODES) {
            int pos = atomicAdd(&g_cursor[col], 1);
            if ((unsigned)pos < (unsigned)N_EDGES)
                g_src[pos] = row;
        }
    }
}

// ---------------- hop1 (gather form, warp per node) ----------------
__global__ void k_hop(const float* __restrict__ hin, float* __restrict__ hout) {
    int gt   = blockIdx.x * blockDim.x + threadIdx.x;
    int node = gt >> 5;
    int lane = gt & 31;
    if (node >= N_NODES) return;

    float di = __ldg(&g_dinv[node]);
    const float4* hin4 = (const float4*)hin;

    float4 v = __ldg(&hin4[(size_t)node * 32 + lane]);
    float4 acc;
    acc.x = di * v.x; acc.y = di * v.y; acc.z = di * v.z; acc.w = di * v.w;

    int s = __ldg(&g_off[node]);
    int e = __ldg(&g_off[node + 1]);
    int k = s;
    for (; k + 3 < e; k += 4) {
        int s0 = __ldg(&g_src[k]);
        int s1 = __ldg(&g_src[k + 1]);
        int s2 = __ldg(&g_src[k + 2]);
        int s3 = __ldg(&g_src[k + 3]);
        float w0 = __ldg(&g_dinv[s0]);
        float w1 = __ldg(&g_dinv[s1]);
        float w2 = __ldg(&g_dinv[s2]);
        float w3 = __ldg(&g_dinv[s3]);
        float4 u0 = __ldg(&hin4[(size_t)s0 * 32 + lane]);
        float4 u1 = __ldg(&hin4[(size_t)s1 * 32 + lane]);
        float4 u2 = __ldg(&hin4[(size_t)s2 * 32 + lane]);
        float4 u3 = __ldg(&hin4[(size_t)s3 * 32 + lane]);
        acc.x += w0 * u0.x + w1 * u1.x + w2 * u2.x + w3 * u3.x;
        acc.y += w0 * u0.y + w1 * u1.y + w2 * u2.y + w3 * u3.y;
        acc.z += w0 * u0.z + w1 * u1.z + w2 * u2.z + w3 * u3.z;
        acc.w += w0 * u0.w + w1 * u1.w + w2 * u2.w + w3 * u3.w;
    }
    for (; k < e; k++) {
        int s0 = __ldg(&g_src[k]);
        float w0 = __ldg(&g_dinv[s0]);
        float4 u0 = __ldg(&hin4[(size_t)s0 * 32 + lane]);
        acc.x += w0 * u0.x; acc.y += w0 * u0.y;
        acc.z += w0 * u0.z; acc.w += w0 * u0.w;
    }
    acc.x *= di; acc.y *= di; acc.z *= di; acc.w *= di;
    ((float4*)hout)[(size_t)node * 32 + lane] = acc;
}

// ---------------- fused hop2 + GEMM + log_softmax ----------------
// Phase 1: gather the block's 128-row A tile (hop2 of h1) into smem [m][k].
// Phase 2: out = log_softmax(A @ W^T + b) with packed fma.rn.f32x2.
#define TM 128
#define TN 128
#define TK 16
#define SMEM_FLOATS (TM * F + TK * TN)   // 64KB A + 8KB B

__global__ __launch_bounds__(256) void k_hop_gemm_lsm(const float* __restrict__ h1,
                                                      const float* __restrict__ W,
                                                      const float* __restrict__ bias,
                                                      float* __restrict__ out) {
    extern __shared__ float smem[];
    float* sA = smem;             // [TM][F]   row-major, pitch F
    float* sB = smem + TM * F;    // [TK][TN]  sB[k][n] = W[n][k]

    int tid   = threadIdx.x;
    int m_blk = blockIdx.x * TM;
    int wid   = tid >> 5;
    int lane  = tid & 31;

    // ---- Phase 1: gather 16 node rows per warp into sA ----
    const float4* hin4 = (const float4*)h1;
    for (int n = 0; n < 16; n++) {
        int lm   = wid * 16 + n;
        int node = m_blk + lm;
        float4 acc = {0.f, 0.f, 0.f, 0.f};
        if (node < N_NODES) {
            float di = __ldg(&g_dinv[node]);
            float4 v = __ldg(&hin4[(size_t)node * 32 + lane]);
            acc.x = di * v.x; acc.y = di * v.y; acc.z = di * v.z; acc.w = di * v.w;

            int s = __ldg(&g_off[node]);
            int e = __ldg(&g_off[node + 1]);
            int k = s;
            for (; k + 3 < e; k += 4) {
                int s0 = __ldg(&g_src[k]);
                int s1 = __ldg(&g_src[k + 1]);
                int s2 = __ldg(&g_src[k + 2]);
                int s3 = __ldg(&g_src[k + 3]);
                float w0 = __ldg(&g_dinv[s0]);
                float w1 = __ldg(&g_dinv[s1]);
                float w2 = __ldg(&g_dinv[s2]);
                float w3 = __ldg(&g_dinv[s3]);
                float4 u0 = __ldg(&hin4[(size_t)s0 * 32 + lane]);
                float4 u1 = __ldg(&hin4[(size_t)s1 * 32 + lane]);
                float4 u2 = __ldg(&hin4[(size_t)s2 * 32 + lane]);
                float4 u3 = __ldg(&hin4[(size_t)s3 * 32 + lane]);
                acc.x += w0 * u0.x + w1 * u1.x + w2 * u2.x + w3 * u3.x;
                acc.y += w0 * u0.y + w1 * u1.y + w2 * u2.y + w3 * u3.y;
                acc.z += w0 * u0.z + w1 * u1.z + w2 * u2.z + w3 * u3.z;
                acc.w += w0 * u0.w + w1 * u1.w + w2 * u2.w + w3 * u3.w;
            }
            for (; k < e; k++) {
                int s0 = __ldg(&g_src[k]);
                float w0 = __ldg(&g_dinv[s0]);
                float4 u0 = __ldg(&hin4[(size_t)s0 * 32 + lane]);
                acc.x += w0 * u0.x; acc.y += w0 * u0.y;
                acc.z += w0 * u0.z; acc.w += w0 * u0.w;
            }
            acc.x *= di; acc.y *= di; acc.z *= di; acc.w *= di;
        }
        *(float4*)&sA[lm * F + lane * 4] = acc;   // coalesced, conflict-free
    }
    __syncthreads();

    // ---- Phase 2: GEMM from smem A + streamed W, fused log_softmax ----
    int lrow = tid >> 1;              // 0..127  (W row = output channel n)
    int lk0  = (tid & 1) * 8;         // 0 or 8
    int tm0  = (tid >> 4) * 8;        // 0..120
    int tn0  = (tid & 15) * 8;        // 0..120

    unsigned long long acc2[8][4];    // acc2[i][j] = (acc[i][2j], acc[i][2j+1])
#pragma unroll
    for (int i = 0; i < 8; i++)
#pragma unroll
        for (int j = 0; j < 4; j++) acc2[i][j] = 0ULL;

    for (int kc = 0; kc < F; kc += TK) {
        const float4* q = (const float4*)(W + (size_t)lrow * F + kc + lk0);
        float4 b0 = q[0], b1 = q[1];

        __syncthreads();   // previous chunk's compute done
        sB[(lk0 + 0) * TN + lrow] = b0.x; sB[(lk0 + 1) * TN + lrow] = b0.y;
        sB[(lk0 + 2) * TN + lrow] = b0.z; sB[(lk0 + 3) * TN + lrow] = b0.w;
        sB[(lk0 + 4) * TN + lrow] = b1.x; sB[(lk0 + 5) * TN + lrow] = b1.y;
        sB[(lk0 + 6) * TN + lrow] = b1.z; sB[(lk0 + 7) * TN + lrow] = b1.w;
        __syncthreads();

#pragma unroll
        for (int kk4 = 0; kk4 < 4; kk4++) {
            float av[8][4];
#pragma unroll
            for (int i = 0; i < 8; i++)
                *(float4*)av[i] = *(const float4*)&sA[(tm0 + i) * F + kc + kk4 * 4];
#pragma unroll
            for (int qq = 0; qq < 4; qq++) {
                int kk = kk4 * 4 + qq;
                ulonglong2 bq0 = *(const ulonglong2*)&sB[kk * TN + tn0];
                ulonglong2 bq1 = *(const ulonglong2*)&sB[kk * TN + tn0 + 4];
                unsigned long long bp[4] = {bq0.x, bq0.y, bq1.x, bq1.y};
#pragma unroll
                for (int i = 0; i < 8; i++) {
                    unsigned long long ap;
                    unsigned int ar = __float_as_uint(av[i][qq]);
                    asm("mov.b64 %0, {%1, %1};" : "=l"(ap) : "r"(ar));
#pragma unroll
                    for (int j = 0; j < 4; j++) {
                        asm("fma.rn.f32x2 %0, %1, %2, %0;"
                            : "+l"(acc2[i][j]) : "l"(ap), "l"(bp[j]));
                    }
                }
            }
        }
    }

    // unpack accumulators
    float acc[8][8];
#pragma unroll
    for (int i = 0; i < 8; i++)
#pragma unroll
        for (int j = 0; j < 4; j++) {
            unsigned int lo, hi;
            asm("mov.b64 {%0, %1}, %2;" : "=r"(lo), "=r"(hi) : "l"(acc2[i][j]));
            acc[i][2 * j]     = __uint_as_float(lo);
            acc[i][2 * j + 1] = __uint_as_float(hi);
        }

    float bj[8];
#pragma unroll
    for (int j = 0; j < 8; j++) bj[j] = __ldg(&bias[tn0 + j]);

#pragma unroll
    for (int i = 0; i < 8; i++) {
#pragma unroll
        for (int j = 0; j < 8; j++) acc[i][j] += bj[j];
    }

    // fused log_softmax per row, half-warp (16-lane) reductions
#pragma unroll
    for (int i = 0; i < 8; i++) {
        float m = acc[i][0];
#pragma unroll
        for (int j = 1; j < 8; j++) m = fmaxf(m, acc[i][j]);
#pragma unroll
        for (int o = 1; o < 16; o <<= 1)
            m = fmaxf(m, __shfl_xor_sync(0xFFFFFFFFu, m, o));

        float s = 0.0f;
#pragma unroll
        for (int j = 0; j < 8; j++) s += expf(acc[i][j] - m);
#pragma unroll
        for (int o = 1; o < 16; o <<= 1)
            s += __shfl_xor_sync(0xFFFFFFFFu, s, o);

        float l = m + logf(s);
#pragma unroll
        for (int j = 0; j < 8; j++) acc[i][j] -= l;
    }

#pragma unroll
    for (int i = 0; i < 8; i++) {
        int gm = m_blk + tm0 + i;
        if (gm < N_NODES) {
            float4 o0, o1;
            o0.x = acc[i][0]; o0.y = acc[i][1]; o0.z = acc[i][2]; o0.w = acc[i][3];
            o1.x = acc[i][4]; o1.y = acc[i][5]; o1.z = acc[i][6]; o1.w = acc[i][7];
            float* op = out + (size_t)gm * F + tn0;
            ((float4*)op)[0] = o0;
            ((float4*)op)[1] = o1;
        }
    }
}

// ---------------- launch ----------------
extern "C" void kernel_launch(void* const* d_in, const int* in_sizes, int n_in,
                              void* d_out, int out_size) {
    const float* x  = (const float*)d_in[0];   // [100000, 128]
    const float* W  = (const float*)d_in[1];   // [128, 128]
    const float* b  = (const float*)d_in[2];   // [128]
    const int*   ei = (const int*)d_in[3];     // [2, 800000] as int32
    float* out = (float*)d_out;

    float* h1;  cudaGetSymbolAddress((void**)&h1, g_h1);
    int*   deg; cudaGetSymbolAddress((void**)&deg, g_deg);

    const int smem_bytes = SMEM_FLOATS * sizeof(float);   // 72KB
    cudaFuncSetAttribute(k_hop_gemm_lsm,
                         cudaFuncAttributeMaxDynamicSharedMemorySize, smem_bytes);

    const int nodes_b = (N_NODES + 255) / 256;
    const int edges_b = (N_EDGES + 255) / 256;
    const int warp_b  = (N_NODES * 32 + 255) / 256;
    const int gemm_b  = (N_NODES + TM - 1) / TM;

    cudaMemsetAsync(deg, 0, N_NODES * sizeof(int));
    k_count<<<edges_b, 256>>>(ei);
    k_scan1<<<NB_SCAN, SCAN_B>>>();
    k_scan2<<<1, 128>>>();
    k_scan3<<<nodes_b, 256>>>();
    k_place<<<edges_b, 256>>>(ei);

    k_hop<<<warp_b, 256>>>(x, h1);
    k_hop_gemm_lsm<<<gemm_b, 256, smem_bytes>>>(h1, W, b, out);
}

// round 10
// speedup vs baseline: 1.5517x; 1.5517x over previous
#include <cuda_runtime.h>
#include <math.h>

#define N_NODES 100000
#define N_EDGES 800000
#define F 128
#define SCAN_B 1024
#define NB_SCAN ((N_NODES + SCAN_B - 1) / SCAN_B)   // 98

// ---------------- static scratch (allocation-free rule) ----------------
__device__ int   g_deg[N_NODES];
__device__ float g_dinv[N_NODES];
__device__ int   g_off[N_NODES + 1];
__device__ int   g_cursor[N_NODES];
__device__ int   g_src[N_EDGES];
__device__ int   g_bsum[NB_SCAN + 32];
__device__ float g_h1[(size_t)N_NODES * F];
__device__ float g_h2[(size_t)N_NODES * F];

// ---------------- degree count (2 edges per thread, int2) ----------------
__global__ void k_count(const int* __restrict__ ei) {
    int e2 = blockIdx.x * blockDim.x + threadIdx.x;
    if (e2 < N_EDGES / 2) {
        int2 c = ((const int2*)(ei + N_EDGES))[e2];
        if ((unsigned)c.x < (unsigned)N_NODES) atomicAdd(&g_deg[c.x], 1);
        if ((unsigned)c.y < (unsigned)N_NODES) atomicAdd(&g_deg[c.y], 1);
    }
}

// ---------------- exclusive scan of g_deg -> g_off ----------------
__global__ void k_scan1() {
    __shared__ int s[SCAN_B];
    int i = blockIdx.x * SCAN_B + threadIdx.x;
    int v = (i < N_NODES) ? g_deg[i] : 0;
    s[threadIdx.x] = v;
    __syncthreads();
    for (int off = 1; off < SCAN_B; off <<= 1) {
        int t = 0;
        if (threadIdx.x >= off) t = s[threadIdx.x - off];
        __syncthreads();
        if (threadIdx.x >= off) s[threadIdx.x] += t;
        __syncthreads();
    }
    if (i < N_NODES) g_off[i] = s[threadIdx.x] - v;  // partial exclusive
    if (threadIdx.x == SCAN_B - 1) g_bsum[blockIdx.x] = s[threadIdx.x];
}

// parallel scan of the 98 block sums (one block, Hillis-Steele)
__global__ void k_scan2() {
    __shared__ int s[128];
    int t = threadIdx.x;
    int v = (t < NB_SCAN) ? g_bsum[t] : 0;
    s[t] = v;
    __syncthreads();
#pragma unroll
    for (int off = 1; off < 128; off <<= 1) {
        int u = 0;
        if (t >= off) u = s[t - off];
        __syncthreads();
        if (t >= off) s[t] += u;
        __syncthreads();
    }
    if (t < NB_SCAN) g_bsum[t] = s[t] - v;  // exclusive
}

__global__ void k_scan3() {
    int i = blockIdx.x * blockDim.x + threadIdx.x;
    if (i < N_NODES) {
        int off = g_off[i] + g_bsum[i / SCAN_B];
        g_off[i] = off;
        g_cursor[i] = off;
        // dinv: degree includes self loop (+1)
        g_dinv[i] = rsqrtf((float)(g_deg[i] + 1));
    }
    if (i == 0) g_off[N_NODES] = N_EDGES;
}

// ---------------- place edges into CSR (2 edges per thread, int2) ----------------
__global__ void k_place(const int* __restrict__ ei) {
    int e2 = blockIdx.x * blockDim.x + threadIdx.x;
    if (e2 < N_EDGES / 2) {
        int2 r = ((const int2*)ei)[e2];
        int2 c = ((const int2*)(ei + N_EDGES))[e2];
        if ((unsigned)r.x < (unsigned)N_NODES && (unsigned)c.x < (unsigned)N_NODES) {
            int pos = atomicAdd(&g_cursor[c.x], 1);
            if ((unsigned)pos < (unsigned)N_EDGES) g_src[pos] = r.x;
        }
        if ((unsigned)r.y < (unsigned)N_NODES && (unsigned)c.y < (unsigned)N_NODES) {
            int pos = atomicAdd(&g_cursor[c.y], 1);
            if ((unsigned)pos < (unsigned)N_EDGES) g_src[pos] = r.y;
        }
    }
}

// ---------------- one propagation hop (gather form, warp per node, 8-wide MLP) ----------------
__global__ void k_hop(const float* __restrict__ hin, float* __restrict__ hout) {
    int gt   = blockIdx.x * blockDim.x + threadIdx.x;
    int node = gt >> 5;
    int lane = gt & 31;
    if (node >= N_NODES) return;

    float di = __ldg(&g_dinv[node]);
    const float4* hin4 = (const float4*)hin;

    // self loop: weight dinv[i]^2 ; edges: dinv[i]*dinv[src]
    float4 v = __ldg(&hin4[(size_t)node * 32 + lane]);
    float4 acc;
    acc.x = di * v.x; acc.y = di * v.y; acc.z = di * v.z; acc.w = di * v.w;

    int s = __ldg(&g_off[node]);
    int e = __ldg(&g_off[node + 1]);
    int k = s;

    // 8-wide software pipeline: 8 outstanding 512B row loads per warp.
    for (; k + 7 < e; k += 8) {
        int   si[8];
        float wi[8];
        float4 ui[8];
#pragma unroll
        for (int t = 0; t < 8; t++) si[t] = __ldg(&g_src[k + t]);
#pragma unroll
        for (int t = 0; t < 8; t++) wi[t] = __ldg(&g_dinv[si[t]]);
#pragma unroll
        for (int t = 0; t < 8; t++) ui[t] = __ldg(&hin4[(size_t)si[t] * 32 + lane]);
#pragma unroll
        for (int t = 0; t < 8; t++) {
            acc.x += wi[t] * ui[t].x;
            acc.y += wi[t] * ui[t].y;
            acc.z += wi[t] * ui[t].z;
            acc.w += wi[t] * ui[t].w;
        }
    }
    for (; k + 3 < e; k += 4) {
        int s0 = __ldg(&g_src[k]);
        int s1 = __ldg(&g_src[k + 1]);
        int s2 = __ldg(&g_src[k + 2]);
        int s3 = __ldg(&g_src[k + 3]);
        float w0 = __ldg(&g_dinv[s0]);
        float w1 = __ldg(&g_dinv[s1]);
        float w2 = __ldg(&g_dinv[s2]);
        float w3 = __ldg(&g_dinv[s3]);
        float4 u0 = __ldg(&hin4[(size_t)s0 * 32 + lane]);
        float4 u1 = __ldg(&hin4[(size_t)s1 * 32 + lane]);
        float4 u2 = __ldg(&hin4[(size_t)s2 * 32 + lane]);
        float4 u3 = __ldg(&hin4[(size_t)s3 * 32 + lane]);
        acc.x += w0 * u0.x + w1 * u1.x + w2 * u2.x + w3 * u3.x;
        acc.y += w0 * u0.y + w1 * u1.y + w2 * u2.y + w3 * u3.y;
        acc.z += w0 * u0.z + w1 * u1.z + w2 * u2.z + w3 * u3.z;
        acc.w += w0 * u0.w + w1 * u1.w + w2 * u2.w + w3 * u3.w;
    }
    for (; k < e; k++) {
        int s0 = __ldg(&g_src[k]);
        float w0 = __ldg(&g_dinv[s0]);
        float4 u0 = __ldg(&hin4[(size_t)s0 * 32 + lane]);
        acc.x += w0 * u0.x; acc.y += w0 * u0.y;
        acc.z += w0 * u0.z; acc.w += w0 * u0.w;
    }
    acc.x *= di; acc.y *= di; acc.z *= di; acc.w *= di;
    ((float4*)hout)[(size_t)node * 32 + lane] = acc;
}

// ---------------- GEMM + fused log_softmax, packed f32x2 FMA ----------------
// out[n][o] = log_softmax_o( sum_k H[n][k]*W[o][k] + b[o] )
#define TM 128
#define TN 128
#define TK 16

__global__ __launch_bounds__(256) void k_gemm_lsm(const float* __restrict__ H,
                                                  const float* __restrict__ W,
                                                  const float* __restrict__ bias,
                                                  float* __restrict__ out) {
    __shared__ float sA[TK][TM];   // sA[k][m]
    __shared__ float sB[TK][TN];   // sB[k][n] = W[n][k]

    int tid   = threadIdx.x;
    int m_blk = blockIdx.x * TM;
    int lrow  = tid >> 1;              // 0..127
    int lk0   = (tid & 1) * 8;         // 0 or 8
    int tm0   = (tid >> 4) * 8;        // 0..120
    int tn0   = (tid & 15) * 8;        // 0..120

    unsigned long long acc2[8][4];     // acc2[i][j] = (acc[i][2j], acc[i][2j+1])
#pragma unroll
    for (int i = 0; i < 8; i++)
#pragma unroll
        for (int j = 0; j < 4; j++) acc2[i][j] = 0ULL;

    for (int kc = 0; kc < F; kc += TK) {
        float4 a0 = {0,0,0,0}, a1 = {0,0,0,0};
        int gm = m_blk + lrow;
        if (gm < N_NODES) {
            const float4* p = (const float4*)(H + (size_t)gm * F + kc + lk0);
            a0 = p[0]; a1 = p[1];
        }
        const float4* q = (const float4*)(W + (size_t)lrow * F + kc + lk0);
        float4 b0 = q[0], b1 = q[1];

        __syncthreads();   // previous tile's compute done
        sA[lk0 + 0][lrow] = a0.x; sA[lk0 + 1][lrow] = a0.y;
        sA[lk0 + 2][lrow] = a0.z; sA[lk0 + 3][lrow] = a0.w;
        sA[lk0 + 4][lrow] = a1.x; sA[lk0 + 5][lrow] = a1.y;
        sA[lk0 + 6][lrow] = a1.z; sA[lk0 + 7][lrow] = a1.w;
        sB[lk0 + 0][lrow] = b0.x; sB[lk0 + 1][lrow] = b0.y;
        sB[lk0 + 2][lrow] = b0.z; sB[lk0 + 3][lrow] = b0.w;
        sB[lk0 + 4][lrow] = b1.x; sB[lk0 + 5][lrow] = b1.y;
        sB[lk0 + 6][lrow] = b1.z; sB[lk0 + 7][lrow] = b1.w;
        __syncthreads();

#pragma unroll
        for (int kk = 0; kk < TK; kk++) {
            float4 av0 = *(const float4*)&sA[kk][tm0];
            float4 av1 = *(const float4*)&sA[kk][tm0 + 4];
            ulonglong2 bq0 = *(const ulonglong2*)&sB[kk][tn0];      // (b0,b1),(b2,b3)
            ulonglong2 bq1 = *(const ulonglong2*)&sB[kk][tn0 + 4];  // (b4,b5),(b6,b7)
            unsigned long long bp[4] = {bq0.x, bq0.y, bq1.x, bq1.y};
            float a[8] = {av0.x, av0.y, av0.z, av0.w, av1.x, av1.y, av1.z, av1.w};
#pragma unroll
            for (int i = 0; i < 8; i++) {
                unsigned long long ap;
                unsigned int ar = __float_as_uint(a[i]);
                asm("mov.b64 %0, {%1, %1};" : "=l"(ap) : "r"(ar));
#pragma unroll
                for (int j = 0; j < 4; j++) {
                    asm("fma.rn.f32x2 %0, %1, %2, %0;"
                        : "+l"(acc2[i][j]) : "l"(ap), "l"(bp[j]));
                }
            }
        }
    }

    // unpack accumulators
    float acc[8][8];
#pragma unroll
    for (int i = 0; i < 8; i++)
#pragma unroll
        for (int j = 0; j < 4; j++) {
            unsigned int lo, hi;
            asm("mov.b64 {%0, %1}, %2;" : "=r"(lo), "=r"(hi) : "l"(acc2[i][j]));
            acc[i][2 * j]     = __uint_as_float(lo);
            acc[i][2 * j + 1] = __uint_as_float(hi);
        }

    float bj[8];
#pragma unroll
    for (int j = 0; j < 8; j++) bj[j] = __ldg(&bias[tn0 + j]);

#pragma unroll
    for (int i = 0; i < 8; i++) {
#pragma unroll
        for (int j = 0; j < 8; j++) acc[i][j] += bj[j];
    }

    // fused log_softmax per row, half-warp (16-lane) reductions
#pragma unroll
    for (int i = 0; i < 8; i++) {
        float m = acc[i][0];
#pragma unroll
        for (int j = 1; j < 8; j++) m = fmaxf(m, acc[i][j]);
#pragma unroll
        for (int o = 1; o < 16; o <<= 1)
            m = fmaxf(m, __shfl_xor_sync(0xFFFFFFFFu, m, o));

        float s = 0.0f;
#pragma unroll
        for (int j = 0; j < 8; j++) s += expf(acc[i][j] - m);
#pragma unroll
        for (int o = 1; o < 16; o <<= 1)
            s += __shfl_xor_sync(0xFFFFFFFFu, s, o);

        float l = m + logf(s);
#pragma unroll
        for (int j = 0; j < 8; j++) acc[i][j] -= l;
    }

#pragma unroll
    for (int i = 0; i < 8; i++) {
        int gm = m_blk + tm0 + i;
        if (gm < N_NODES) {
            float4 o0, o1;
            o0.x = acc[i][0]; o0.y = acc[i][1]; o0.z = acc[i][2]; o0.w = acc[i][3];
            o1.x = acc[i][4]; o1.y = acc[i][5]; o1.z = acc[i][6]; o1.w = acc[i][7];
            float* op = out + (size_t)gm * F + tn0;
            ((float4*)op)[0] = o0;
            ((float4*)op)[1] = o1;
        }
    }
}

// ---------------- launch ----------------
extern "C" void kernel_launch(void* const* d_in, const int* in_sizes, int n_in,
                              void* d_out, int out_size) {
    const float* x  = (const float*)d_in[0];   // [100000, 128]
    const float* W  = (const float*)d_in[1];   // [128, 128]
    const float* b  = (const float*)d_in[2];   // [128]
    const int*   ei = (const int*)d_in[3];     // [2, 800000] as int32
    float* out = (float*)d_out;

    float* h1;  cudaGetSymbolAddress((void**)&h1, g_h1);
    float* h2;  cudaGetSymbolAddress((void**)&h2, g_h2);
    int*   deg; cudaGetSymbolAddress((void**)&deg, g_deg);

    const int nodes_b  = (N_NODES + 255) / 256;
    const int edges2_b = (N_EDGES / 2 + 255) / 256;
    const int warp_b   = (N_NODES * 32 + 255) / 256;
    const int gemm_b   = (N_NODES + TM - 1) / TM;

    cudaMemsetAsync(deg, 0, N_NODES * sizeof(int));
    k_count<<<edges2_b, 256>>>(ei);
    k_scan1<<<NB_SCAN, SCAN_B>>>();
    k_scan2<<<1, 128>>>();
    k_scan3<<<nodes_b, 256>>>();
    k_place<<<edges2_b, 256>>>(ei);

    k_hop<<<warp_b, 256>>>(x, h1);
    k_hop<<<warp_b, 256>>>(h1, h2);

    k_gemm_lsm<<<gemm_b, 256>>>(h2, W, b, out);
}

// round 13
// speedup vs baseline: 1.6598x; 1.0696x over previous
#include <cuda_runtime.h>
#include <math.h>
#include <stdint.h>

#define N_NODES 100000
#define N_EDGES 800000
#define F 128
#define SCAN_B 1024
#define NB_SCAN ((N_NODES + SCAN_B - 1) / SCAN_B)   // 98

// ---------------- static scratch (allocation-free rule) ----------------
__device__ int   g_deg[N_NODES];
__device__ float g_dinv[N_NODES];
__device__ int   g_off[N_NODES + 1];
__device__ int   g_cursor[N_NODES];
__device__ int   g_src[N_EDGES];
__device__ int   g_bsum[NB_SCAN + 32];
__device__ float g_h1[(size_t)N_NODES * F];
__device__ float g_h2[(size_t)N_NODES * F];

// ---------------- degree count (2 edges per thread, int2) ----------------
__global__ void k_count(const int* __restrict__ ei) {
    int e2 = blockIdx.x * blockDim.x + threadIdx.x;
    if (e2 < N_EDGES / 2) {
        int2 c = ((const int2*)(ei + N_EDGES))[e2];
        if ((unsigned)c.x < (unsigned)N_NODES) atomicAdd(&g_deg[c.x], 1);
        if ((unsigned)c.y < (unsigned)N_NODES) atomicAdd(&g_deg[c.y], 1);
    }
}

// ---------------- exclusive scan of g_deg -> g_off ----------------
__global__ void k_scan1() {
    __shared__ int s[SCAN_B];
    int i = blockIdx.x * SCAN_B + threadIdx.x;
    int v = (i < N_NODES) ? g_deg[i] : 0;
    s[threadIdx.x] = v;
    __syncthreads();
    for (int off = 1; off < SCAN_B; off <<= 1) {
        int t = 0;
        if (threadIdx.x >= off) t = s[threadIdx.x - off];
        __syncthreads();
        if (threadIdx.x >= off) s[threadIdx.x] += t;
        __syncthreads();
    }
    if (i < N_NODES) g_off[i] = s[threadIdx.x] - v;
    if (threadIdx.x == SCAN_B - 1) g_bsum[blockIdx.x] = s[threadIdx.x];
}

__global__ void k_scan2() {
    __shared__ int s[128];
    int t = threadIdx.x;
    int v = (t < NB_SCAN) ? g_bsum[t] : 0;
    s[t] = v;
    __syncthreads();
#pragma unroll
    for (int off = 1; off < 128; off <<= 1) {
        int u = 0;
        if (t >= off) u = s[t - off];
        __syncthreads();
        if (t >= off) s[t] += u;
        __syncthreads();
    }
    if (t < NB_SCAN) g_bsum[t] = s[t] - v;
}

__global__ void k_scan3() {
    int i = blockIdx.x * blockDim.x + threadIdx.x;
    if (i < N_NODES) {
        int off = g_off[i] + g_bsum[i / SCAN_B];
        g_off[i] = off;
        g_cursor[i] = off;
        g_dinv[i] = rsqrtf((float)(g_deg[i] + 1));
    }
    if (i == 0) g_off[N_NODES] = N_EDGES;
}

// ---------------- place edges into CSR (2 edges per thread, int2) ----------------
__global__ void k_place(const int* __restrict__ ei) {
    int e2 = blockIdx.x * blockDim.x + threadIdx.x;
    if (e2 < N_EDGES / 2) {
        int2 r = ((const int2*)ei)[e2];
        int2 c = ((const int2*)(ei + N_EDGES))[e2];
        if ((unsigned)r.x < (unsigned)N_NODES && (unsigned)c.x < (unsigned)N_NODES) {
            int pos = atomicAdd(&g_cursor[c.x], 1);
            if ((unsigned)pos < (unsigned)N_EDGES) g_src[pos] = r.x;
        }
        if ((unsigned)r.y < (unsigned)N_NODES && (unsigned)c.y < (unsigned)N_NODES) {
            int pos = atomicAdd(&g_cursor[c.y], 1);
            if ((unsigned)pos < (unsigned)N_EDGES) g_src[pos] = r.y;
        }
    }
}

// ---------------- one propagation hop (gather form, warp per node, 8-wide MLP) ----------------
__global__ void k_hop(const float* __restrict__ hin, float* __restrict__ hout) {
    int gt   = blockIdx.x * blockDim.x + threadIdx.x;
    int node = gt >> 5;
    int lane = gt & 31;
    if (node >= N_NODES) return;

    float di = __ldg(&g_dinv[node]);
    const float4* hin4 = (const float4*)hin;

    float4 v = __ldg(&hin4[(size_t)node * 32 + lane]);
    float4 acc;
    acc.x = di * v.x; acc.y = di * v.y; acc.z = di * v.z; acc.w = di * v.w;

    int s = __ldg(&g_off[node]);
    int e = __ldg(&g_off[node + 1]);
    int k = s;

    for (; k + 7 < e; k += 8) {
        int   si[8];
        float wi[8];
        float4 ui[8];
#pragma unroll
        for (int t = 0; t < 8; t++) si[t] = __ldg(&g_src[k + t]);
#pragma unroll
        for (int t = 0; t < 8; t++) wi[t] = __ldg(&g_dinv[si[t]]);
#pragma unroll
        for (int t = 0; t < 8; t++) ui[t] = __ldg(&hin4[(size_t)si[t] * 32 + lane]);
#pragma unroll
        for (int t = 0; t < 8; t++) {
            acc.x += wi[t] * ui[t].x;
            acc.y += wi[t] * ui[t].y;
            acc.z += wi[t] * ui[t].z;
            acc.w += wi[t] * ui[t].w;
        }
    }
    for (; k + 3 < e; k += 4) {
        int s0 = __ldg(&g_src[k]);
        int s1 = __ldg(&g_src[k + 1]);
        int s2 = __ldg(&g_src[k + 2]);
        int s3 = __ldg(&g_src[k + 3]);
        float w0 = __ldg(&g_dinv[s0]);
        float w1 = __ldg(&g_dinv[s1]);
        float w2 = __ldg(&g_dinv[s2]);
        float w3 = __ldg(&g_dinv[s3]);
        float4 u0 = __ldg(&hin4[(size_t)s0 * 32 + lane]);
        float4 u1 = __ldg(&hin4[(size_t)s1 * 32 + lane]);
        float4 u2 = __ldg(&hin4[(size_t)s2 * 32 + lane]);
        float4 u3 = __ldg(&hin4[(size_t)s3 * 32 + lane]);
        acc.x += w0 * u0.x + w1 * u1.x + w2 * u2.x + w3 * u3.x;
        acc.y += w0 * u0.y + w1 * u1.y + w2 * u2.y + w3 * u3.y;
        acc.z += w0 * u0.z + w1 * u1.z + w2 * u2.z + w3 * u3.z;
        acc.w += w0 * u0.w + w1 * u1.w + w2 * u2.w + w3 * u3.w;
    }
    for (; k < e; k++) {
        int s0 = __ldg(&g_src[k]);
        float w0 = __ldg(&g_dinv[s0]);
        float4 u0 = __ldg(&hin4[(size_t)s0 * 32 + lane]);
        acc.x += w0 * u0.x; acc.y += w0 * u0.y;
        acc.z += w0 * u0.z; acc.w += w0 * u0.w;
    }
    acc.x *= di; acc.y *= di; acc.z *= di; acc.w *= di;
    ((float4*)hout)[(size_t)node * 32 + lane] = acc;
}

// ============================================================================
// mma.sync tf32 GEMM + fused bias + log_softmax (family-portable tensor path)
// Per block: 64 rows of H x W^T -> 64x128 logits -> log_softmax -> out.
// A and W staged in smem as tf32, pitch 132 (conflict-free fragment LDS).
// ============================================================================
#define GTM 64
#define PITCH 132
#define SW_OFF   0                       // W: 128 x PITCH tf32
#define SA_OFF   (128 * PITCH)           // A: 64 x PITCH tf32
#define SBIAS_OFF (SA_OFF + GTM * PITCH) // bias: 128 f32
#define SMEM_U32 (SBIAS_OFF + 128 + 16)

__device__ __forceinline__ uint32_t f2tf32(float f) {
    uint32_t r;
    asm("cvt.rna.tf32.f32 %0, %1;" : "=r"(r) : "f"(f));
    return r;
}

__global__ __launch_bounds__(256) void k_mma_lsm(const float* __restrict__ H,
                                                 const float* __restrict__ W,
                                                 const float* __restrict__ bias,
                                                 float* __restrict__ out) {
    extern __shared__ uint32_t smem[];
    uint32_t* sW = smem + SW_OFF;
    uint32_t* sA = smem + SA_OFF;
    float*    sBias = (float*)(smem + SBIAS_OFF);

    int tid   = threadIdx.x;
    int wid   = tid >> 5;
    int lane  = tid & 31;
    int m_blk = blockIdx.x * GTM;

    // ---- stage W (tf32), A tile (tf32), bias into smem ----
    for (int idx = tid; idx < 128 * 32; idx += 256) {
        int row = idx >> 5, c4 = idx & 31;
        float4 w = __ldg((const float4*)(W + (size_t)row * F) + c4);
        uint32_t* d = &sW[row * PITCH + c4 * 4];
        d[0] = f2tf32(w.x); d[1] = f2tf32(w.y); d[2] = f2tf32(w.z); d[3] = f2tf32(w.w);
    }
    for (int idx = tid; idx < GTM * 32; idx += 256) {
        int row = idx >> 5, c4 = idx & 31;
        int gm = m_blk + row;
        float4 a = {0.f, 0.f, 0.f, 0.f};
        if (gm < N_NODES) a = __ldg((const float4*)(H + (size_t)gm * F) + c4);
        uint32_t* d = &sA[row * PITCH + c4 * 4];
        d[0] = f2tf32(a.x); d[1] = f2tf32(a.y); d[2] = f2tf32(a.z); d[3] = f2tf32(a.w);
    }
    for (int i = tid; i < F; i += 256) sBias[i] = __ldg(&bias[i]);
    __syncthreads();

    // ---- warp tiling: 2x4 warps, each 32(m) x 32(n) ----
    int wm = (wid >> 2) * 32;          // 0 or 32
    int wn = (wid & 3) * 32;           // 0,32,64,96
    int gID = lane >> 2;               // 0..7
    int tID = lane & 3;                // 0..3

    float acc[2][4][4];
#pragma unroll
    for (int mi = 0; mi < 2; mi++)
#pragma unroll
        for (int t = 0; t < 4; t++)
#pragma unroll
            for (int r = 0; r < 4; r++) acc[mi][t][r] = 0.0f;

#pragma unroll
    for (int ks = 0; ks < 16; ks++) {
        int k0 = ks * 8;
        uint32_t a[2][4];
#pragma unroll
        for (int mi = 0; mi < 2; mi++) {
            const uint32_t* ar0 = &sA[(wm + mi * 16 + gID) * PITCH + k0];
            const uint32_t* ar1 = &sA[(wm + mi * 16 + gID + 8) * PITCH + k0];
            a[mi][0] = ar0[tID];      // (row g,    col t)
            a[mi][1] = ar1[tID];      // (row g+8,  col t)
            a[mi][2] = ar0[tID + 4];  // (row g,    col t+4)
            a[mi][3] = ar1[tID + 4];  // (row g+8,  col t+4)
        }
        uint32_t b[4][2];
#pragma unroll
        for (int t = 0; t < 4; t++) {
            const uint32_t* br = &sW[(wn + t * 8 + gID) * PITCH + k0];
            b[t][0] = br[tID];        // B[k=t,   n=g]
            b[t][1] = br[tID + 4];    // B[k=t+4, n=g]
        }
#pragma unroll
        for (int mi = 0; mi < 2; mi++)
#pragma unroll
            for (int t = 0; t < 4; t++) {
                asm volatile(
                    "mma.sync.aligned.m16n8k8.row.col.f32.tf32.tf32.f32 "
                    "{%0,%1,%2,%3}, {%4,%5,%6,%7}, {%8,%9}, {%0,%1,%2,%3};"
                    : "+f"(acc[mi][t][0]), "+f"(acc[mi][t][1]),
                      "+f"(acc[mi][t][2]), "+f"(acc[mi][t][3])
                    : "r"(a[mi][0]), "r"(a[mi][1]), "r"(a[mi][2]), "r"(a[mi][3]),
                      "r"(b[t][0]), "r"(b[t][1]));
            }
    }
    __syncthreads();   // everyone done reading sA -> reuse as logits buffer

    // ---- scatter accumulators to smem logits [64][PITCH] ----
    float* sOut = (float*)sA;
#pragma unroll
    for (int mi = 0; mi < 2; mi++) {
#pragma unroll
        for (int t = 0; t < 4; t++) {
            int col  = wn + t * 8 + tID * 2;
            int row0 = wm + mi * 16 + gID;
            int row1 = row0 + 8;
            float2 lo = {acc[mi][t][0], acc[mi][t][1]};
            float2 hi = {acc[mi][t][2], acc[mi][t][3]};
            *(float2*)&sOut[row0 * PITCH + col] = lo;
            *(float2*)&sOut[row1 * PITCH + col] = hi;
        }
    }
    __syncthreads();

    // ---- warp-per-row log_softmax (bias folded into read) ----
#pragma unroll
    for (int rr = 0; rr < 8; rr++) {
        int row = wid * 8 + rr;
        float4 v = ((float4*)&sOut[row * PITCH])[lane];
        float4 bj = ((float4*)sBias)[lane];
        v.x += bj.x; v.y += bj.y; v.z += bj.z; v.w += bj.w;

        float m = fmaxf(fmaxf(v.x, v.y), fmaxf(v.z, v.w));
#pragma unroll
        for (int o = 16; o; o >>= 1) m = fmaxf(m, __shfl_xor_sync(0xFFFFFFFFu, m, o));
        float s = expf(v.x - m) + expf(v.y - m) + expf(v.z - m) + expf(v.w - m);
#pragma unroll
        for (int o = 16; o; o >>= 1) s += __shfl_xor_sync(0xFFFFFFFFu, s, o);
        float l = m + logf(s);

        int gm = m_blk + row;
        if (gm < N_NODES) {
            float4 o4;
            o4.x = v.x - l; o4.y = v.y - l; o4.z = v.z - l; o4.w = v.w - l;
            ((float4*)(out + (size_t)gm * F))[lane] = o4;
        }
    }
}

// ---------------- launch ----------------
extern "C" void kernel_launch(void* const* d_in, const int* in_sizes, int n_in,
                              void* d_out, int out_size) {
    const float* x  = (const float*)d_in[0];   // [100000, 128]
    const float* W  = (const float*)d_in[1];   // [128, 128]
    const float* b  = (const float*)d_in[2];   // [128]
    const int*   ei = (const int*)d_in[3];     // [2, 800000] as int32
    float* out = (float*)d_out;

    float* h1;  cudaGetSymbolAddress((void**)&h1, g_h1);
    float* h2;  cudaGetSymbolAddress((void**)&h2, g_h2);
    int*   deg; cudaGetSymbolAddress((void**)&deg, g_deg);

    const int smem_bytes = SMEM_U32 * 4;   // ~102KB
    cudaFuncSetAttribute(k_mma_lsm,
                         cudaFuncAttributeMaxDynamicSharedMemorySize, smem_bytes);

    const int nodes_b  = (N_NODES + 255) / 256;
    const int edges2_b = (N_EDGES / 2 + 255) / 256;
    const int warp_b   = (N_NODES * 32 + 255) / 256;
    const int gemm_b   = (N_NODES + GTM - 1) / GTM;

    cudaMemsetAsync(deg, 0, N_NODES * sizeof(int));
    k_count<<<edges2_b, 256>>>(ei);
    k_scan1<<<NB_SCAN, SCAN_B>>>();
    k_scan2<<<1, 128>>>();
    k_scan3<<<nodes_b, 256>>>();
    k_place<<<edges2_b, 256>>>(ei);

    k_hop<<<warp_b, 256>>>(x, h1);
    k_hop<<<warp_b, 256>>>(h1, h2);

    k_mma_lsm<<<gemm_b, 256, smem_bytes>>>(h2, W, b, out);
}

// round 15
// speedup vs baseline: 2.2539x; 1.3579x over previous
#include <cuda_runtime.h>
#include <cuda_fp16.h>
#include <math.h>
#include <stdint.h>

#define N_NODES 100000
#define N_EDGES 800000
#define F 128
#define SCAN_B 1024
#define NB_SCAN ((N_NODES + SCAN_B - 1) / SCAN_B)   // 98

// ---------------- static scratch (allocation-free rule) ----------------
__device__ int    g_deg[N_NODES];
__device__ float  g_dinv[N_NODES];
__device__ int    g_off[N_NODES + 1];
__device__ int    g_cursor[N_NODES];
__device__ int    g_src[N_EDGES];
__device__ int    g_bsum[NB_SCAN + 32];
__device__ __half g_xh[(size_t)N_NODES * F];
__device__ __half g_h1[(size_t)N_NODES * F];
__device__ __half g_h2[(size_t)N_NODES * F];

// ---------------- fp32 -> fp16 conversion (x) ----------------
__global__ void k_f2h(const float* __restrict__ x, __half* __restrict__ xh) {
    int i = blockIdx.x * blockDim.x + threadIdx.x;
    if (i < N_NODES * F / 4) {
        float4 v = __ldg(&((const float4*)x)[i]);
        __half2 h0 = __floats2half2_rn(v.x, v.y);
        __half2 h1 = __floats2half2_rn(v.z, v.w);
        uint2 o;
        o.x = *(uint32_t*)&h0;
        o.y = *(uint32_t*)&h1;
        ((uint2*)xh)[i] = o;
    }
}

// ---------------- degree count (2 edges per thread, int2) ----------------
__global__ void k_count(const int* __restrict__ ei) {
    int e2 = blockIdx.x * blockDim.x + threadIdx.x;
    if (e2 < N_EDGES / 2) {
        int2 c = ((const int2*)(ei + N_EDGES))[e2];
        if ((unsigned)c.x < (unsigned)N_NODES) atomicAdd(&g_deg[c.x], 1);
        if ((unsigned)c.y < (unsigned)N_NODES) atomicAdd(&g_deg[c.y], 1);
    }
}

// ---------------- exclusive scan of g_deg -> g_off ----------------
__global__ void k_scan1() {
    __shared__ int s[SCAN_B];
    int i = blockIdx.x * SCAN_B + threadIdx.x;
    int v = (i < N_NODES) ? g_deg[i] : 0;
    s[threadIdx.x] = v;
    __syncthreads();
    for (int off = 1; off < SCAN_B; off <<= 1) {
        int t = 0;
        if (threadIdx.x >= off) t = s[threadIdx.x - off];
        __syncthreads();
        if (threadIdx.x >= off) s[threadIdx.x] += t;
        __syncthreads();
    }
    if (i < N_NODES) g_off[i] = s[threadIdx.x] - v;
    if (threadIdx.x == SCAN_B - 1) g_bsum[blockIdx.x] = s[threadIdx.x];
}

__global__ void k_scan2() {
    __shared__ int s[128];
    int t = threadIdx.x;
    int v = (t < NB_SCAN) ? g_bsum[t] : 0;
    s[t] = v;
    __syncthreads();
#pragma unroll
    for (int off = 1; off < 128; off <<= 1) {
        int u = 0;
        if (t >= off) u = s[t - off];
        __syncthreads();
        if (t >= off) s[t] += u;
        __syncthreads();
    }
    if (t < NB_SCAN) g_bsum[t] = s[t] - v;
}

__global__ void k_scan3() {
    int i = blockIdx.x * blockDim.x + threadIdx.x;
    if (i < N_NODES) {
        int off = g_off[i] + g_bsum[i / SCAN_B];
        g_off[i] = off;
        g_cursor[i] = off;
        g_dinv[i] = rsqrtf((float)(g_deg[i] + 1));
    }
    if (i == 0) g_off[N_NODES] = N_EDGES;
}

// ---------------- place edges into CSR (2 edges per thread, int2) ----------------
__global__ void k_place(const int* __restrict__ ei) {
    int e2 = blockIdx.x * blockDim.x + threadIdx.x;
    if (e2 < N_EDGES / 2) {
        int2 r = ((const int2*)ei)[e2];
        int2 c = ((const int2*)(ei + N_EDGES))[e2];
        if ((unsigned)r.x < (unsigned)N_NODES && (unsigned)c.x < (unsigned)N_NODES) {
            int pos = atomicAdd(&g_cursor[c.x], 1);
            if ((unsigned)pos < (unsigned)N_EDGES) g_src[pos] = r.x;
        }
        if ((unsigned)r.y < (unsigned)N_NODES && (unsigned)c.y < (unsigned)N_NODES) {
            int pos = atomicAdd(&g_cursor[c.y], 1);
            if ((unsigned)pos < (unsigned)N_EDGES) g_src[pos] = r.y;
        }
    }
}

// ---------------- fp16 hop (gather form, warp per node, 8-wide MLP) ----------------
__device__ __forceinline__ float4 u2f4(uint2 u) {
    float2 a = __half22float2(*(__half2*)&u.x);
    float2 b = __half22float2(*(__half2*)&u.y);
    float4 r; r.x = a.x; r.y = a.y; r.z = b.x; r.w = b.y;
    return r;
}

__global__ void k_hop_h(const __half* __restrict__ hin, __half* __restrict__ hout) {
    int gt   = blockIdx.x * blockDim.x + threadIdx.x;
    int node = gt >> 5;
    int lane = gt & 31;
    if (node >= N_NODES) return;

    float di = __ldg(&g_dinv[node]);
    const uint2* hin2 = (const uint2*)hin;   // 32 uint2 per 128-half row

    float4 vf = u2f4(__ldg(&hin2[(size_t)node * 32 + lane]));
    float4 acc;
    acc.x = di * vf.x; acc.y = di * vf.y; acc.z = di * vf.z; acc.w = di * vf.w;

    int s = __ldg(&g_off[node]);
    int e = __ldg(&g_off[node + 1]);
    int k = s;

    for (; k + 7 < e; k += 8) {
        int   si[8];
        float wi[8];
        uint2 ui[8];
#pragma unroll
        for (int t = 0; t < 8; t++) si[t] = __ldg(&g_src[k + t]);
#pragma unroll
        for (int t = 0; t < 8; t++) wi[t] = __ldg(&g_dinv[si[t]]);
#pragma unroll
        for (int t = 0; t < 8; t++) ui[t] = __ldg(&hin2[(size_t)si[t] * 32 + lane]);
#pragma unroll
        for (int t = 0; t < 8; t++) {
            float4 uf = u2f4(ui[t]);
            acc.x += wi[t] * uf.x;
            acc.y += wi[t] * uf.y;
            acc.z += wi[t] * uf.z;
            acc.w += wi[t] * uf.w;
        }
    }
    for (; k < e; k++) {
        int s0 = __ldg(&g_src[k]);
        float w0 = __ldg(&g_dinv[s0]);
        float4 uf = u2f4(__ldg(&hin2[(size_t)s0 * 32 + lane]));
        acc.x += w0 * uf.x; acc.y += w0 * uf.y;
        acc.z += w0 * uf.z; acc.w += w0 * uf.w;
    }
    acc.x *= di; acc.y *= di; acc.z *= di; acc.w *= di;

    __half2 o0 = __floats2half2_rn(acc.x, acc.y);
    __half2 o1 = __floats2half2_rn(acc.z, acc.w);
    uint2 o;
    o.x = *(uint32_t*)&o0;
    o.y = *(uint32_t*)&o1;
    ((uint2*)hout)[(size_t)node * 32 + lane] = o;
}

// ============================================================================
// fp16 mma.sync m16n8k16 GEMM + fused bias + log_softmax
// Per block: 64 rows of H (fp16) x W^T -> 64x128 logits -> log_softmax -> out.
// ============================================================================
#define GTM 64
#define PITCH_H 136                      // halves; 272B row stride -> conflict-free frags
#define PITCH_F 132                      // floats; epilogue logits pitch
// smem layout (bytes):
#define SW_B    0                                      // W fp16: 128 * PITCH_H * 2 = 34816
#define SA_B    (128 * PITCH_H * 2)                    // A fp16: 64 * PITCH_H * 2 = 17408
#define SBIAS_B (SA_B + GTM * PITCH_H * 2)             // bias fp32: 512
#define SMEM_B_TOT (SBIAS_B + 512 + 32)

__global__ __launch_bounds__(256) void k_mma_lsm(const __half* __restrict__ H,
                                                 const float* __restrict__ W,
                                                 const float* __restrict__ bias,
                                                 float* __restrict__ out) {
    extern __shared__ char smem[];
    __half* sW = (__half*)(smem + SW_B);
    __half* sA = (__half*)(smem + SA_B);
    float*  sBias = (float*)(smem + SBIAS_B);

    int tid   = threadIdx.x;
    int wid   = tid >> 5;
    int lane  = tid & 31;
    int m_blk = blockIdx.x * GTM;

    // ---- stage W (f32->f16), A tile (f16 copy), bias ----
    for (int idx = tid; idx < 128 * 32; idx += 256) {
        int row = idx >> 5, c4 = idx & 31;
        float4 w = __ldg((const float4*)(W + (size_t)row * F) + c4);
        __half2 h0 = __floats2half2_rn(w.x, w.y);
        __half2 h1 = __floats2half2_rn(w.z, w.w);
        uint2 o; o.x = *(uint32_t*)&h0; o.y = *(uint32_t*)&h1;
        *(uint2*)&sW[row * PITCH_H + c4 * 4] = o;
    }
    for (int idx = tid; idx < GTM * 16; idx += 256) {
        int row = idx >> 4, c8 = idx & 15;       // uint4 = 8 halves
        int gm = m_blk + row;
        uint4 a = {0u, 0u, 0u, 0u};
        if (gm < N_NODES)
            a = __ldg((const uint4*)(H + (size_t)gm * F) + c8);
        *(uint4*)&sA[row * PITCH_H + c8 * 8] = a;
    }
    for (int i = tid; i < F; i += 256) sBias[i] = __ldg(&bias[i]);
    __syncthreads();

    // ---- warp tiling: 2x4 warps, each 32(m) x 32(n) ----
    int wm  = (wid >> 2) * 32;         // 0 or 32
    int wn  = (wid & 3) * 32;          // 0,32,64,96
    int gID = lane >> 2;               // 0..7
    int tID = lane & 3;                // 0..3

    float acc[2][4][4];
#pragma unroll
    for (int mi = 0; mi < 2; mi++)
#pragma unroll
        for (int t = 0; t < 4; t++)
#pragma unroll
            for (int r = 0; r < 4; r++) acc[mi][t][r] = 0.0f;

#pragma unroll
    for (int ks = 0; ks < 8; ks++) {
        int k0 = ks * 16;
        uint32_t a[2][4];
#pragma unroll
        for (int mi = 0; mi < 2; mi++) {
            const __half* ar0 = &sA[(wm + mi * 16 + gID) * PITCH_H + k0];
            const __half* ar1 = &sA[(wm + mi * 16 + gID + 8) * PITCH_H + k0];
            a[mi][0] = *(const uint32_t*)&ar0[2 * tID];       // row g,   k=2t,2t+1
            a[mi][1] = *(const uint32_t*)&ar1[2 * tID];       // row g+8
            a[mi][2] = *(const uint32_t*)&ar0[2 * tID + 8];   // row g,   k=2t+8,+9
            a[mi][3] = *(const uint32_t*)&ar1[2 * tID + 8];   // row g+8
        }
        uint32_t b[4][2];
#pragma unroll
        for (int t = 0; t < 4; t++) {
            const __half* br = &sW[(wn + t * 8 + gID) * PITCH_H + k0];
            b[t][0] = *(const uint32_t*)&br[2 * tID];         // k=2t,2t+1  n=g
            b[t][1] = *(const uint32_t*)&br[2 * tID + 8];     // k=2t+8,+9
        }
#pragma unroll
        for (int mi = 0; mi < 2; mi++)
#pragma unroll
            for (int t = 0; t < 4; t++) {
                asm volatile(
                    "mma.sync.aligned.m16n8k16.row.col.f32.f16.f16.f32 "
                    "{%0,%1,%2,%3}, {%4,%5,%6,%7}, {%8,%9}, {%0,%1,%2,%3};"
                    : "+f"(acc[mi][t][0]), "+f"(acc[mi][t][1]),
                      "+f"(acc[mi][t][2]), "+f"(acc[mi][t][3])
                    : "r"(a[mi][0]), "r"(a[mi][1]), "r"(a[mi][2]), "r"(a[mi][3]),
                      "r"(b[t][0]), "r"(b[t][1]));
            }
    }
    __syncthreads();   // done reading sW/sA -> reuse sW region for logits

    // ---- scatter accumulators to smem logits [64][PITCH_F] ----
    float* sOut = (float*)(smem + SW_B);   // 64*132*4 = 33792 <= 34816
#pragma unroll
    for (int mi = 0; mi < 2; mi++) {
#pragma unroll
        for (int t = 0; t < 4; t++) {
            int col  = wn + t * 8 + tID * 2;
            int row0 = wm + mi * 16 + gID;
            int row1 = row0 + 8;
            float2 lo = {acc[mi][t][0], acc[mi][t][1]};
            float2 hi = {acc[mi][t][2], acc[mi][t][3]};
            *(float2*)&sOut[row0 * PITCH_F + col] = lo;
            *(float2*)&sOut[row1 * PITCH_F + col] = hi;
        }
    }
    __syncthreads();

    // ---- warp-per-row log_softmax (bias folded into read) ----
#pragma unroll
    for (int rr = 0; rr < 8; rr++) {
        int row = wid * 8 + rr;
        float4 v = ((float4*)&sOut[row * PITCH_F])[lane];
        float4 bj = ((float4*)sBias)[lane];
        v.x += bj.x; v.y += bj.y; v.z += bj.z; v.w += bj.w;

        float m = fmaxf(fmaxf(v.x, v.y), fmaxf(v.z, v.w));
#pragma unroll
        for (int o = 16; o; o >>= 1) m = fmaxf(m, __shfl_xor_sync(0xFFFFFFFFu, m, o));
        float s = expf(v.x - m) + expf(v.y - m) + expf(v.z - m) + expf(v.w - m);
#pragma unroll
        for (int o = 16; o; o >>= 1) s += __shfl_xor_sync(0xFFFFFFFFu, s, o);
        float l = m + logf(s);

        int gm = m_blk + row;
        if (gm < N_NODES) {
            float4 o4;
            o4.x = v.x - l; o4.y = v.y - l; o4.z = v.z - l; o4.w = v.w - l;
            ((float4*)(out + (size_t)gm * F))[lane] = o4;
        }
    }
}

// ---------------- launch ----------------
extern "C" void kernel_launch(void* const* d_in, const int* in_sizes, int n_in,
                              void* d_out, int out_size) {
    const float* x  = (const float*)d_in[0];   // [100000, 128]
    const float* W  = (const float*)d_in[1];   // [128, 128]
    const float* b  = (const float*)d_in[2];   // [128]
    const int*   ei = (const int*)d_in[3];     // [2, 800000] as int32
    float* out = (float*)d_out;

    __half* xh; cudaGetSymbolAddress((void**)&xh, g_xh);
    __half* h1; cudaGetSymbolAddress((void**)&h1, g_h1);
    __half* h2; cudaGetSymbolAddress((void**)&h2, g_h2);
    int*   deg; cudaGetSymbolAddress((void**)&deg, g_deg);

    cudaFuncSetAttribute(k_mma_lsm,
                         cudaFuncAttributeMaxDynamicSharedMemorySize, SMEM_B_TOT);

    const int nodes_b  = (N_NODES + 255) / 256;
    const int edges2_b = (N_EDGES / 2 + 255) / 256;
    const int warp_b   = (N_NODES * 32 + 255) / 256;
    const int f2h_b    = (N_NODES * F / 4 + 255) / 256;
    const int gemm_b   = (N_NODES + GTM - 1) / GTM;

    cudaMemsetAsync(deg, 0, N_NODES * sizeof(int));
    k_f2h<<<f2h_b, 256>>>(x, xh);
    k_count<<<edges2_b, 256>>>(ei);
    k_scan1<<<NB_SCAN, SCAN_B>>>();
    k_scan2<<<1, 128>>>();
    k_scan3<<<nodes_b, 256>>>();
    k_place<<<edges2_b, 256>>>(ei);

    k_hop_h<<<warp_b, 256>>>(xh, h1);
    k_hop_h<<<warp_b, 256>>>(h1, h2);

    k_mma_lsm<<<gemm_b, 256, SMEM_B_TOT>>>(h2, W, b, out);
}

// round 17
// speedup vs baseline: 2.4757x; 1.0984x over previous
#include <cuda_runtime.h>
#include <cuda_fp16.h>
#include <math.h>
#include <stdint.h>

#define N_NODES 100000
#define N_EDGES 800000
#define F 128
#define SCAN_B 1024
#define NB_SCAN ((N_NODES + SCAN_B - 1) / SCAN_B)   // 98

// ---------------- static scratch (allocation-free rule) ----------------
__device__ int    g_deg[N_NODES];
__device__ float  g_dinv[N_NODES];
__device__ int    g_off[N_NODES + 1];
__device__ int    g_cursor[N_NODES];
__device__ int    g_src[N_EDGES];
__device__ int    g_bsum[NB_SCAN + 32];
__device__ __half g_xh[(size_t)N_NODES * F];
__device__ __half g_wh[F * F];
__device__ __half g_h1[(size_t)N_NODES * F];
__device__ __half g_h2[(size_t)N_NODES * F];

// ---------------- fused prep: x->fp16, W->fp16, degree count ----------------
__global__ void k_prep(const float* __restrict__ x, const float* __restrict__ W,
                       const int* __restrict__ ei) {
    int i = blockIdx.x * blockDim.x + threadIdx.x;

    if (i < N_NODES * F / 4) {
        float4 v = __ldg(&((const float4*)x)[i]);
        __half2 h0 = __floats2half2_rn(v.x, v.y);
        __half2 h1 = __floats2half2_rn(v.z, v.w);
        uint2 o;
        o.x = *(uint32_t*)&h0;
        o.y = *(uint32_t*)&h1;
        ((uint2*)g_xh)[i] = o;
    }
    if (i < F * F / 4) {
        float4 v = __ldg(&((const float4*)W)[i]);
        __half2 h0 = __floats2half2_rn(v.x, v.y);
        __half2 h1 = __floats2half2_rn(v.z, v.w);
        uint2 o;
        o.x = *(uint32_t*)&h0;
        o.y = *(uint32_t*)&h1;
        ((uint2*)g_wh)[i] = o;
    }
    if (i < N_EDGES / 2) {
        int2 c = ((const int2*)(ei + N_EDGES))[i];
        if ((unsigned)c.x < (unsigned)N_NODES) atomicAdd(&g_deg[c.x], 1);
        if ((unsigned)c.y < (unsigned)N_NODES) atomicAdd(&g_deg[c.y], 1);
    }
}

// ---------------- exclusive scan of g_deg -> g_off ----------------
__global__ void k_scan1() {
    __shared__ int s[SCAN_B];
    int i = blockIdx.x * SCAN_B + threadIdx.x;
    int v = (i < N_NODES) ? g_deg[i] : 0;
    s[threadIdx.x] = v;
    __syncthreads();
    for (int off = 1; off < SCAN_B; off <<= 1) {
        int t = 0;
        if (threadIdx.x >= off) t = s[threadIdx.x - off];
        __syncthreads();
        if (threadIdx.x >= off) s[threadIdx.x] += t;
        __syncthreads();
    }
    if (i < N_NODES) g_off[i] = s[threadIdx.x] - v;
    if (threadIdx.x == SCAN_B - 1) g_bsum[blockIdx.x] = s[threadIdx.x];
}

// scan3 with inlined block-sum scan (every block redundantly scans the 98 sums)
__global__ void k_scan3() {
    __shared__ int si[128];
    __shared__ int se[128];
    int t = threadIdx.x;
    if (t < 128) {
        int v = (t < NB_SCAN) ? g_bsum[t] : 0;
        si[t] = v;
        se[t] = v;   // stash own value
    }
    __syncthreads();
#pragma unroll
    for (int off = 1; off < 128; off <<= 1) {
        int u = 0;
        if (t < 128 && t >= off) u = si[t - off];
        __syncthreads();
        if (t < 128 && t >= off) si[t] += u;
        __syncthreads();
    }
    if (t < 128) se[t] = si[t] - se[t];   // exclusive prefix
    __syncthreads();

    int i = blockIdx.x * blockDim.x + t;
    if (i < N_NODES) {
        int off = g_off[i] + se[i / SCAN_B];
        g_off[i] = off;
        g_cursor[i] = off;
        g_dinv[i] = rsqrtf((float)(g_deg[i] + 1));
    }
    if (i == 0) g_off[N_NODES] = N_EDGES;
}

// ---------------- place edges into CSR (2 edges per thread, int2) ----------------
__global__ void k_place(const int* __restrict__ ei) {
    int e2 = blockIdx.x * blockDim.x + threadIdx.x;
    if (e2 < N_EDGES / 2) {
        int2 r = ((const int2*)ei)[e2];
        int2 c = ((const int2*)(ei + N_EDGES))[e2];
        if ((unsigned)r.x < (unsigned)N_NODES && (unsigned)c.x < (unsigned)N_NODES) {
            int pos = atomicAdd(&g_cursor[c.x], 1);
            if ((unsigned)pos < (unsigned)N_EDGES) g_src[pos] = r.x;
        }
        if ((unsigned)r.y < (unsigned)N_NODES && (unsigned)c.y < (unsigned)N_NODES) {
            int pos = atomicAdd(&g_cursor[c.y], 1);
            if ((unsigned)pos < (unsigned)N_EDGES) g_src[pos] = r.y;
        }
    }
}

// ---------------- fp16 hop (gather form, warp per node, 8-wide MLP) ----------------
__device__ __forceinline__ float4 u2f4(uint2 u) {
    float2 a = __half22float2(*(__half2*)&u.x);
    float2 b = __half22float2(*(__half2*)&u.y);
    float4 r; r.x = a.x; r.y = a.y; r.z = b.x; r.w = b.y;
    return r;
}

__global__ void k_hop_h(const __half* __restrict__ hin, __half* __restrict__ hout) {
    int gt   = blockIdx.x * blockDim.x + threadIdx.x;
    int node = gt >> 5;
    int lane = gt & 31;
    if (node >= N_NODES) return;

    float di = __ldg(&g_dinv[node]);
    const uint2* hin2 = (const uint2*)hin;

    float4 vf = u2f4(__ldg(&hin2[(size_t)node * 32 + lane]));
    float4 acc;
    acc.x = di * vf.x; acc.y = di * vf.y; acc.z = di * vf.z; acc.w = di * vf.w;

    int s = __ldg(&g_off[node]);
    int e = __ldg(&g_off[node + 1]);
    int k = s;

    for (; k + 7 < e; k += 8) {
        int   si[8];
        float wi[8];
        uint2 ui[8];
#pragma unroll
        for (int t = 0; t < 8; t++) si[t] = __ldg(&g_src[k + t]);
#pragma unroll
        for (int t = 0; t < 8; t++) wi[t] = __ldg(&g_dinv[si[t]]);
#pragma unroll
        for (int t = 0; t < 8; t++) ui[t] = __ldg(&hin2[(size_t)si[t] * 32 + lane]);
#pragma unroll
        for (int t = 0; t < 8; t++) {
            float4 uf = u2f4(ui[t]);
            acc.x += wi[t] * uf.x;
            acc.y += wi[t] * uf.y;
            acc.z += wi[t] * uf.z;
            acc.w += wi[t] * uf.w;
        }
    }
    for (; k < e; k++) {
        int s0 = __ldg(&g_src[k]);
        float w0 = __ldg(&g_dinv[s0]);
        float4 uf = u2f4(__ldg(&hin2[(size_t)s0 * 32 + lane]));
        acc.x += w0 * uf.x; acc.y += w0 * uf.y;
        acc.z += w0 * uf.z; acc.w += w0 * uf.w;
    }
    acc.x *= di; acc.y *= di; acc.z *= di; acc.w *= di;

    __half2 o0 = __floats2half2_rn(acc.x, acc.y);
    __half2 o1 = __floats2half2_rn(acc.z, acc.w);
    uint2 o;
    o.x = *(uint32_t*)&o0;
    o.y = *(uint32_t*)&o1;
    ((uint2*)hout)[(size_t)node * 32 + lane] = o;
}

// ============================================================================
// fp16 mma.sync m16n8k16 GEMM + fused bias + log_softmax
// Per block: 64 rows of H (fp16) x W^T (fp16, pre-converted) -> log_softmax.
// ============================================================================
#define GTM 64
#define PITCH_H 136
#define PITCH_F 132
#define SW_B    0                                      // W fp16: 128*PITCH_H*2 = 34816
#define SA_B    (128 * PITCH_H * 2)                    // A fp16: 64*PITCH_H*2 = 17408
#define SBIAS_B (SA_B + GTM * PITCH_H * 2)
#define SMEM_B_TOT (SBIAS_B + 512 + 32)

__global__ __launch_bounds__(256) void k_mma_lsm(const __half* __restrict__ H,
                                                 const __half* __restrict__ Wh,
                                                 const float* __restrict__ bias,
                                                 float* __restrict__ out) {
    extern __shared__ char smem[];
    __half* sW = (__half*)(smem + SW_B);
    __half* sA = (__half*)(smem + SA_B);
    float*  sBias = (float*)(smem + SBIAS_B);

    int tid   = threadIdx.x;
    int wid   = tid >> 5;
    int lane  = tid & 31;
    int m_blk = blockIdx.x * GTM;

    // ---- stage W (fp16 copy), A tile (fp16 copy), bias ----
    for (int idx = tid; idx < 128 * 16; idx += 256) {
        int row = idx >> 4, c8 = idx & 15;               // uint4 = 8 halves
        uint4 w = __ldg((const uint4*)Wh + (size_t)row * 16 + c8);
        *(uint4*)&sW[row * PITCH_H + c8 * 8] = w;
    }
    for (int idx = tid; idx < GTM * 16; idx += 256) {
        int row = idx >> 4, c8 = idx & 15;
        int gm = m_blk + row;
        uint4 a = {0u, 0u, 0u, 0u};
        if (gm < N_NODES)
            a = __ldg((const uint4*)(H + (size_t)gm * F) + c8);
        *(uint4*)&sA[row * PITCH_H + c8 * 8] = a;
    }
    for (int i = tid; i < F; i += 256) sBias[i] = __ldg(&bias[i]);
    __syncthreads();

    // ---- warp tiling: 2x4 warps, each 32(m) x 32(n) ----
    int wm  = (wid >> 2) * 32;
    int wn  = (wid & 3) * 32;
    int gID = lane >> 2;
    int tID = lane & 3;

    float acc[2][4][4];
#pragma unroll
    for (int mi = 0; mi < 2; mi++)
#pragma unroll
        for (int t = 0; t < 4; t++)
#pragma unroll
            for (int r = 0; r < 4; r++) acc[mi][t][r] = 0.0f;

#pragma unroll
    for (int ks = 0; ks < 8; ks++) {
        int k0 = ks * 16;
        uint32_t a[2][4];
#pragma unroll
        for (int mi = 0; mi < 2; mi++) {
            const __half* ar0 = &sA[(wm + mi * 16 + gID) * PITCH_H + k0];
            const __half* ar1 = &sA[(wm + mi * 16 + gID + 8) * PITCH_H + k0];
            a[mi][0] = *(const uint32_t*)&ar0[2 * tID];
            a[mi][1] = *(const uint32_t*)&ar1[2 * tID];
            a[mi][2] = *(const uint32_t*)&ar0[2 * tID + 8];
            a[mi][3] = *(const uint32_t*)&ar1[2 * tID + 8];
        }
        uint32_t b[4][2];
#pragma unroll
        for (int t = 0; t < 4; t++) {
            const __half* br = &sW[(wn + t * 8 + gID) * PITCH_H + k0];
            b[t][0] = *(const uint32_t*)&br[2 * tID];
            b[t][1] = *(const uint32_t*)&br[2 * tID + 8];
        }
#pragma unroll
        for (int mi = 0; mi < 2; mi++)
#pragma unroll
            for (int t = 0; t < 4; t++) {
                asm volatile(
                    "mma.sync.aligned.m16n8k16.row.col.f32.f16.f16.f32 "
                    "{%0,%1,%2,%3}, {%4,%5,%6,%7}, {%8,%9}, {%0,%1,%2,%3};"
                    : "+f"(acc[mi][t][0]), "+f"(acc[mi][t][1]),
                      "+f"(acc[mi][t][2]), "+f"(acc[mi][t][3])
                    : "r"(a[mi][0]), "r"(a[mi][1]), "r"(a[mi][2]), "r"(a[mi][3]),
                      "r"(b[t][0]), "r"(b[t][1]));
            }
    }
    __syncthreads();   // done reading sW/sA -> reuse sW region for logits

    // ---- scatter accumulators to smem logits [64][PITCH_F] ----
    float* sOut = (float*)(smem + SW_B);   // 64*132*4 = 33792 <= 34816
#pragma unroll
    for (int mi = 0; mi < 2; mi++) {
#pragma unroll
        for (int t = 0; t < 4; t++) {
            int col  = wn + t * 8 + tID * 2;
            int row0 = wm + mi * 16 + gID;
            int row1 = row0 + 8;
            float2 lo = {acc[mi][t][0], acc[mi][t][1]};
            float2 hi = {acc[mi][t][2], acc[mi][t][3]};
            *(float2*)&sOut[row0 * PITCH_F + col] = lo;
            *(float2*)&sOut[row1 * PITCH_F + col] = hi;
        }
    }
    __syncthreads();

    // ---- warp-per-row log_softmax (bias folded into read) ----
#pragma unroll
    for (int rr = 0; rr < 8; rr++) {
        int row = wid * 8 + rr;
        float4 v = ((float4*)&sOut[row * PITCH_F])[lane];
        float4 bj = ((float4*)sBias)[lane];
        v.x += bj.x; v.y += bj.y; v.z += bj.z; v.w += bj.w;

        float m = fmaxf(fmaxf(v.x, v.y), fmaxf(v.z, v.w));
#pragma unroll
        for (int o = 16; o; o >>= 1) m = fmaxf(m, __shfl_xor_sync(0xFFFFFFFFu, m, o));
        float s = expf(v.x - m) + expf(v.y - m) + expf(v.z - m) + expf(v.w - m);
#pragma unroll
        for (int o = 16; o; o >>= 1) s += __shfl_xor_sync(0xFFFFFFFFu, s, o);
        float l = m + logf(s);

        int gm = m_blk + row;
        if (gm < N_NODES) {
            float4 o4;
            o4.x = v.x - l; o4.y = v.y - l; o4.z = v.z - l; o4.w = v.w - l;
            ((float4*)(out + (size_t)gm * F))[lane] = o4;
        }
    }
}

// ---------------- launch ----------------
extern "C" void kernel_launch(void* const* d_in, const int* in_sizes, int n_in,
                              void* d_out, int out_size) {
    const float* x  = (const float*)d_in[0];   // [100000, 128]
    const float* W  = (const float*)d_in[1];   // [128, 128]
    const float* b  = (const float*)d_in[2];   // [128]
    const int*   ei = (const int*)d_in[3];     // [2, 800000] as int32
    float* out = (float*)d_out;

    __half* xh; cudaGetSymbolAddress((void**)&xh, g_xh);
    __half* wh; cudaGetSymbolAddress((void**)&wh, g_wh);
    __half* h1; cudaGetSymbolAddress((void**)&h1, g_h1);
    __half* h2; cudaGetSymbolAddress((void**)&h2, g_h2);
    int*   deg; cudaGetSymbolAddress((void**)&deg, g_deg);

    cudaFuncSetAttribute(k_mma_lsm,
                         cudaFuncAttributeMaxDynamicSharedMemorySize, SMEM_B_TOT);

    const int nodes_b  = (N_NODES + 255) / 256;
    const int edges2_b = (N_EDGES / 2 + 255) / 256;
    const int warp_b   = (N_NODES * 32 + 255) / 256;
    const int prep_b   = (N_NODES * F / 4 + 255) / 256;
    const int gemm_b   = (N_NODES + GTM - 1) / GTM;

    cudaMemsetAsync(deg, 0, N_NODES * sizeof(int));
    k_prep<<<prep_b, 256>>>(x, W, ei);
    k_scan1<<<NB_SCAN, SCAN_B>>>();
    k_scan3<<<nodes_b, 256>>>();
    k_place<<<edges2_b, 256>>>(ei);

    k_hop_h<<<warp_b, 256>>>(xh, h1);
    k_hop_h<<<warp_b, 256>>>(h1, h2);

    k_mma_lsm<<<gemm_b, 256, SMEM_B_TOT>>>(h2, wh, b, out);
}